// round 1
// baseline (speedup 1.0000x reference)
#include <cuda_runtime.h>
#include <math.h>

// FLC pooling: out = Re[ ifft2( centered-crop( fftshift(fft2(x, fwd)) ), fwd ) ]
// Reduced analytically to a real separable 113-tap convolution + rank-1 correction.
//
// a[d] = (1/224) * sum_{k=-56}^{55} e^{2pi i k d / 224}
//   a[0] = 1/2 ; a[even d != 0] = 0
//   a[odd d]  = eps(d) * (cot(pi d/224) - i)/224,  eps = +1 if d%4==1 else -1
// Imag parts collapse to: out[m,n] = out1[m,n] - (-1)^(m+n) * C / 224^2
//   C = sum_{h odd, w odd} sigma(h) sigma(w) x[h,w], sigma(+1 if %4==1 else -1)

#define NIMG 1024          // 16*64
#define HH   224
#define HO   112

__device__ float g_rodd[112];               // Re a[2i+1]
__device__ float g_C[NIMG];                 // per-image correction scalar
__device__ float g_T[(size_t)NIMG * HH * HO]; // stage-1 intermediate [img][h][n]

__global__ void init_coef_kernel() {
    int i = threadIdx.x;
    if (i < 112) {
        int d = 2 * i + 1;
        double th = 3.14159265358979323846 * (double)d / 224.0;
        double c  = cos(th) / sin(th);
        double eps = (i & 1) ? -1.0 : 1.0;   // d%4==1 <=> i even
        g_rodd[i] = (float)(eps * c / 224.0);
    }
}

__global__ __launch_bounds__(256) void compute_C_kernel(const float* __restrict__ x) {
    int img = blockIdx.x;
    const float* xi = x + (size_t)img * HH * HH;
    float s = 0.f;
    for (int i = threadIdx.x; i < 112 * 112; i += 256) {
        int a = i / 112, b = i % 112;
        float v = xi[(2 * a + 1) * HH + (2 * b + 1)];
        s += ((a + b) & 1) ? -v : v;
    }
    __shared__ float red[256];
    red[threadIdx.x] = s;
    __syncthreads();
    for (int st = 128; st > 0; st >>= 1) {
        if (threadIdx.x < st) red[threadIdx.x] += red[threadIdx.x + st];
        __syncthreads();
    }
    if (threadIdx.x == 0) g_C[img] = red[0];
}

// ---------------- Stage 1: row convolution  T[R][n] = conv_w(x[R][:]) -------
// block = 32 rows; blockDim (32,4); thread tile = 8 rows x 4 n.
#define ROWS1 32
__global__ __launch_bounds__(128) void stage1_kernel(const float* __restrict__ x) {
    __shared__ float xs[ROWS1 * HH];   // 28 KB
    __shared__ float rs2[256];         // duplicated rodd table, zero-padded
    int tx = threadIdx.x, ty = threadIdx.y;
    int tid = ty * 32 + tx;

    for (int i = tid; i < 256; i += 128)
        rs2[i] = (i < 224) ? g_rodd[(i >= 112) ? (i - 112) : i] : 0.f;

    size_t rowbase = (size_t)blockIdx.x * ROWS1;   // = img*224 + h0 (never crosses image)
    const float* src = x + rowbase * HH;
    for (int i = tid; i < ROWS1 * HH; i += 128) xs[i] = src[i];
    __syncthreads();

    const float* myrow = &xs[ty * 8 * HH];

    float acc[8][4];
    #pragma unroll
    for (int k = 0; k < 4; k++) {
        int n = tx + 32 * k;
        int ne = (n < 112) ? n : 111;
        #pragma unroll
        for (int rr = 0; rr < 8; rr++)
            acc[rr][k] = 0.5f * myrow[rr * HH + 2 * ne];
    }

    #pragma unroll 4
    for (int j = 0; j < 112; j++) {
        float cf[4];
        #pragma unroll
        for (int k = 0; k < 4; k++) cf[k] = rs2[tx + 32 * k + 111 - j];
        float xv[8];
        #pragma unroll
        for (int rr = 0; rr < 8; rr++) xv[rr] = myrow[rr * HH + 2 * j + 1];
        #pragma unroll
        for (int rr = 0; rr < 8; rr++)
            #pragma unroll
            for (int k = 0; k < 4; k++)
                acc[rr][k] += cf[k] * xv[rr];
    }

    #pragma unroll
    for (int k = 0; k < 4; k++) {
        int n = tx + 32 * k;
        if (n < 112) {
            #pragma unroll
            for (int rr = 0; rr < 8; rr++)
                g_T[(rowbase + ty * 8 + rr) * HO + n] = acc[rr][k];
        }
    }
}

// ---------------- Stage 2: column convolution + correction ------------------
// block = one image; dynamic smem: Todd[112][112] + rs2[256] = 51200 B
__global__ __launch_bounds__(128) void stage2_kernel(float* __restrict__ out) {
    extern __shared__ float sm[];
    float* sTodd = sm;            // [112*112]
    float* rs2   = sm + 112 * 112;

    int tx = threadIdx.x, ty = threadIdx.y;
    int tid = ty * 32 + tx;
    int img = blockIdx.x;
    const float* Timg = g_T + (size_t)img * HH * HO;

    for (int i = tid; i < 256; i += 128)
        rs2[i] = (i < 224) ? g_rodd[(i >= 112) ? (i - 112) : i] : 0.f;
    for (int i = tid; i < 112 * 112; i += 128) {
        int j = i / 112, n = i % 112;
        sTodd[i] = Timg[(2 * j + 1) * HO + n];
    }
    __syncthreads();

    float corr = g_C[img] * (1.0f / 50176.0f);

    int nn[4], ne[4];
    #pragma unroll
    for (int k = 0; k < 4; k++) {
        nn[k] = tx + 32 * k;
        ne[k] = (nn[k] < 112) ? nn[k] : 111;
    }

    for (int p = 0; p < 4; p++) {            // m = ty*28 + p*7 + rr, rr<7
        int mbase = ty * 28 + p * 7;
        float acc[7][4];
        #pragma unroll
        for (int rr = 0; rr < 7; rr++) {
            int m = mbase + rr;
            #pragma unroll
            for (int k = 0; k < 4; k++)
                acc[rr][k] = 0.5f * Timg[(2 * m) * HO + ne[k]];
        }
        #pragma unroll 4
        for (int j = 0; j < 112; j++) {
            float tv[4];
            #pragma unroll
            for (int k = 0; k < 4; k++) tv[k] = sTodd[j * 112 + ne[k]];
            float cf[7];
            #pragma unroll
            for (int rr = 0; rr < 7; rr++) cf[rr] = rs2[mbase + rr + 111 - j];
            #pragma unroll
            for (int rr = 0; rr < 7; rr++)
                #pragma unroll
                for (int k = 0; k < 4; k++)
                    acc[rr][k] += cf[rr] * tv[k];
        }
        #pragma unroll
        for (int rr = 0; rr < 7; rr++) {
            int m = mbase + rr;
            #pragma unroll
            for (int k = 0; k < 4; k++) {
                if (nn[k] < 112) {
                    float v = acc[rr][k] - (((m + nn[k]) & 1) ? -corr : corr);
                    out[(size_t)img * HO * HO + m * HO + nn[k]] = v;
                }
            }
        }
    }
}

extern "C" void kernel_launch(void* const* d_in, const int* in_sizes, int n_in,
                              void* d_out, int out_size) {
    (void)in_sizes; (void)n_in; (void)out_size;
    const float* x = (const float*)d_in[0];
    float* out = (float*)d_out;

    static const int SMEM2 = (112 * 112 + 256) * 4;  // 51200 B
    cudaFuncSetAttribute(stage2_kernel,
                         cudaFuncAttributeMaxDynamicSharedMemorySize, SMEM2);

    init_coef_kernel<<<1, 128>>>();
    compute_C_kernel<<<NIMG, 256>>>(x);
    stage1_kernel<<<NIMG * HH / ROWS1, dim3(32, 4)>>>(x);
    stage2_kernel<<<NIMG, dim3(32, 4), SMEM2>>>(out);
}